// round 10
// baseline (speedup 1.0000x reference)
#include <cuda_runtime.h>
#include <cuda_bf16.h>
#include <cuda_fp16.h>
#include <cstdint>

#define B_    4
#define C_    128
#define H_    96
#define W_    96
#define HW_   (H_*W_)          // 9216
#define P_    (B_*HW_)         // 36864
#define E_    8
#define NEX   9
#define WP_   98
#define HP_   98
#define HWP_  (HP_*WP_)        // 9604
#define PPAD_ (B_*HWP_)        // 38416
#define NCHUNK 36              // K=1152 in chunks of 32

// prep kernel block partition
#define NB_HALO   194          // 4b * 388 halo px * 32 (uint2 over 128 ci) / 256
#define NB_NHWC   4608         // 288 hw-tiles * 4 ci-tiles * 4 b
#define NB_REPACK 2592
#define NB_PREP   (NB_HALO + NB_NHWC + NB_REPACK)

// ---------------- device globals (no allocation) --------------------------
__device__ __half   g_xh[PPAD_*C_];            // fp16 NHWC padded activations (9.8MB)
__device__ uint32_t g_wBf[NEX*NCHUNK*2048];    // fp16 B frags: [e][chunk]     (2.6MB)
__device__ float    g_bias[NEX*C_];
__device__ int      g_count[E_];
__device__ unsigned long long g_list[E_][P_];  // (w_bits<<32)|(slot<<20)|pid
__device__ float    g_partial[3*P_*C_];        // [slot][pid][co]  (56.6MB)

// ---------------- helpers --------------------------------------------------
__device__ __forceinline__ void mma_fp16(float* c, const uint32_t* a, const uint32_t* b) {
    asm volatile(
        "mma.sync.aligned.m16n8k16.row.col.f32.f16.f16.f32 "
        "{%0,%1,%2,%3}, {%4,%5,%6,%7}, {%8,%9}, {%0,%1,%2,%3};"
        : "+f"(c[0]), "+f"(c[1]), "+f"(c[2]), "+f"(c[3])
        : "r"(a[0]), "r"(a[1]), "r"(a[2]), "r"(a[3]), "r"(b[0]), "r"(b[1]));
}

__device__ __forceinline__ uint32_t smem_u32(const void* p) {
    uint32_t a;
    asm("{ .reg .u64 t; cvta.to.shared.u64 t, %1; cvt.u32.u64 %0, t; }" : "=r"(a) : "l"(p));
    return a;
}
__device__ __forceinline__ void cp_async16(uint32_t dst, const void* src) {
    asm volatile("cp.async.cg.shared.global [%0], [%1], 16;" :: "r"(dst), "l"(src) : "memory");
}
#define CP_COMMIT() asm volatile("cp.async.commit_group;" ::: "memory")
#define CP_WAIT0()  asm volatile("cp.async.wait_group 0;" ::: "memory")

// ---------------- fused prep: init + halo zero + nhwc fp16 + repackB ------
__global__ void k_prep(const float* __restrict__ x,
                       const float* __restrict__ ew, const float* __restrict__ sw,
                       const float* __restrict__ eb, const float* __restrict__ sb) {
    const int bx = blockIdx.x;
    const int tid = threadIdx.x;

    if (bx < NB_HALO) {
        // ---- counters (block 0) ----
        if (bx == 0 && tid < E_) g_count[tid] = 0;
        // ---- zero halo ring: 4 b * 388 px * 32 uint2 (4 halfs each) ----
        int g = bx*256 + tid;                 // < 49664
        int ci8 = g & 31;                     // uint2 index over 128 ci
        int j   = (g >> 5) % 388;
        int b   = g / (388*32);
        int hp, wp;
        if (j < 98)        { hp = 0;  wp = j; }
        else if (j < 196)  { hp = 97; wp = j - 98; }
        else { int k = j - 196; hp = 1 + (k >> 1); wp = (k & 1) ? 97 : 0; }
        int pp = b*HWP_ + hp*WP_ + wp;
        ((uint2*)(g_xh + (size_t)pp*C_))[ci8] = make_uint2(0u, 0u);
        return;
    }
    if (bx < NB_HALO + NB_NHWC) {
        // ---- NCHW fp32 -> NHWC fp16 padded (interior) ----
        __shared__ float t[32][33];
        int s = bx - NB_HALO;
        int hw0 = (s % 288) * 32;
        int ci0 = ((s / 288) & 3) * 32;
        int b   = s / (288*4);
        #pragma unroll
        for (int r = 0; r < 4; r++) {
            int ci = (tid >> 5) + r*8, hw = tid & 31;
            t[ci][hw] = x[((b*C_) + ci0 + ci)*HW_ + hw0 + hw];
        }
        __syncthreads();
        #pragma unroll
        for (int r = 0; r < 4; r++) {
            int hwl = (tid >> 5) + r*8, cil = tid & 31;
            int hw = hw0 + hwl, h = hw / W_, w = hw - h*W_;
            int pad = b*HWP_ + (h+1)*WP_ + (w+1);
            g_xh[(size_t)pad*C_ + ci0 + cil] = __float2half_rn(t[cil][hwl]);
        }
        return;
    }
    // ---- repack weights -> fp16 mma fragment order + bias ----
    int idx = (bx - NB_HALO - NB_NHWC)*256 + tid;
    const int total = NEX*C_*9*64;
    if (idx < total) {
        int cip = idx & 63;
        int tap = (idx >> 6) % 9;
        int co  = (idx / (64*9)) & 127;
        int e   = idx / (64*9*C_);
        int ci  = cip * 2;
        float v0, v1;
        if (e < 8) {
            int base = ((e*C_ + co)*C_ + ci)*9 + tap;
            v0 = ew[base]; v1 = ew[base + 9];
        } else {
            int base = (co*C_ + ci)*9 + tap;
            v0 = sw[base]; v1 = sw[base + 9];
        }
        uint32_t h0 = (uint32_t)__half_as_ushort(__float2half_rn(v0));
        uint32_t h1 = (uint32_t)__half_as_ushort(__float2half_rn(v1));
        int k_abs = tap*C_ + ci;
        int chunk = k_abs >> 5;
        int k0 = k_abs & 31;
        int ks = k0 >> 4;
        int lane = ((co & 7) << 2) + ((k0 & 7) >> 1);
        int reg  = (k0 >> 3) & 1;
        int nt   = co >> 3;
        size_t di = (size_t)(e*NCHUNK + chunk)*2048 + ((ks*16 + nt)*32 + lane)*2 + reg;
        g_wBf[di] = h0 | (h1 << 16);
    }
    if (idx < NEX*C_) {
        int ex = idx >> 7, co = idx & 127;
        g_bias[idx] = (ex < 8) ? eb[idx] : sb[co];
    }
}

// ---------------- gate: fp32 NCHW conv(8) + sigmoid + top2 + softmax ------
// MUST stay fp32 on the ORIGINAL x: expert selection is a decision boundary;
// fp16 inputs flip near-tied top-2 picks and blow up rel_err (R7 lesson).
__global__ void k_gate(const float* __restrict__ x, const float* __restrict__ gw,
                       const float* __restrict__ gbias) {
    __shared__ float sgw[E_*C_*9];
    for (int i = threadIdx.x; i < E_*C_*9; i += blockDim.x) sgw[i] = gw[i];
    __syncthreads();

    int pid = blockIdx.x * blockDim.x + threadIdx.x;
    if (pid >= P_) return;
    int b = pid / HW_, hw = pid - b*HW_;
    int h = hw / W_, w = hw - h*W_;
    const float* xb = x + (size_t)b*C_*HW_ + hw;
    bool hm = h > 0, hp = h < H_-1, wm = w > 0, wp = w < W_-1;

    float acc[E_];
    #pragma unroll
    for (int e = 0; e < E_; e++) acc[e] = 0.f;
    for (int ci = 0; ci < C_; ci++) {
        const float* xp = xb + ci*HW_;
        float xv[9];
        xv[0] = (hm && wm) ? xp[-W_-1] : 0.f;
        xv[1] =  hm        ? xp[-W_]   : 0.f;
        xv[2] = (hm && wp) ? xp[-W_+1] : 0.f;
        xv[3] =  wm        ? xp[-1]    : 0.f;
        xv[4] =              xp[0];
        xv[5] =  wp        ? xp[1]     : 0.f;
        xv[6] = (hp && wm) ? xp[W_-1]  : 0.f;
        xv[7] =  hp        ? xp[W_]    : 0.f;
        xv[8] = (hp && wp) ? xp[W_+1]  : 0.f;
        #pragma unroll
        for (int e = 0; e < E_; e++) {
            const float* wp9 = &sgw[(e*C_ + ci)*9];
            float a = acc[e];
            #pragma unroll
            for (int t = 0; t < 9; t++) a = fmaf(xv[t], wp9[t], a);
            acc[e] = a;
        }
    }
    float s[E_], bsc[E_];
    #pragma unroll
    for (int e = 0; e < E_; e++) {
        s[e]   = 1.f / (1.f + expf(-acc[e]));
        bsc[e] = s[e] + gbias[e];
    }
    int e0 = 0;
    #pragma unroll
    for (int e = 1; e < E_; e++) if (bsc[e] > bsc[e0]) e0 = e;
    int e1 = (e0 == 0) ? 1 : 0;
    #pragma unroll
    for (int e = 0; e < E_; e++) if (e != e0 && bsc[e] > bsc[e1]) e1 = e;
    float m = fmaxf(s[e0], s[e1]);
    float d0 = expf(s[e0]-m), d1 = expf(s[e1]-m);
    float inv = 1.f / (d0 + d1);
    int p0 = atomicAdd(&g_count[e0], 1);
    g_list[e0][p0] = (((unsigned long long)__float_as_uint(d0*inv)) << 32) | (unsigned)pid;
    int p1 = atomicAdd(&g_count[e1], 1);
    g_list[e1][p1] = (((unsigned long long)__float_as_uint(d1*inv)) << 32) | (unsigned)(pid | (1u<<20));
}

// ---------------- fp16 mma.sync expert GEMM (pipelined, single-pass) ------
// CTA: 128 pixels x 128 couts, one expert. 8 warps in 2(M)x4(N).
__global__ __launch_bounds__(256, 2)
void k_mma() {
    const int e    = blockIdx.y;
    const int tile = blockIdx.x;
    const int n    = (e < 8) ? g_count[e] : P_;
    if (tile * 128 >= n) return;

    extern __shared__ uint32_t dsm[];
    uint32_t* sAp = dsm;          // 2 stages x 2048 u32
    uint32_t* sBp = dsm + 4096;   // 2 stages x 2048 u32
    __shared__ int   s_pid[128];
    __shared__ int   s_pp[128];
    __shared__ float s_wt[128];
    __shared__ float s_bias[128];

    const int tid = threadIdx.x;
    if (tid < 128) {
        int idx = tile*128 + tid;
        int pid = 0, slot = 0; float wt = 0.f;
        if (e < 8) {
            if (idx < n) {
                unsigned long long v = g_list[e][idx];
                wt   = __uint_as_float((unsigned)(v >> 32));
                unsigned lo = (unsigned)v;
                pid  = lo & 0xFFFFF;
                slot = (lo >> 20) & 1;
            }
        } else { pid = idx; wt = 1.f; slot = 2; }
        int b = pid / HW_, hw = pid - b*HW_;
        int h = hw / W_, w = hw - h*W_;
        s_pp[tid]   = (wt != 0.f) ? (b*HWP_ + (h+1)*WP_ + (w+1)) : (WP_ + 1);
        s_pid[tid]  = pid | (slot << 20);
        s_wt[tid]   = wt;
        s_bias[tid] = g_bias[e*C_ + tid];
    }
    __syncthreads();

    const int lane = tid & 31, wid = tid >> 5;
    const int wm = wid >> 2, wn = wid & 3;

    float c[4][4][4];
    #pragma unroll
    for (int i = 0; i < 4; i++)
        #pragma unroll
        for (int j = 0; j < 4; j++)
            #pragma unroll
            for (int k = 0; k < 4; k++) c[i][j][k] = 0.f;

    const int m_row = tid >> 3;      // A gather: 8 threads per pixel row
    const int kq    = tid & 7;       // each covers 4 ci (8 bytes fp16)
    const uint32_t sB_byte = smem_u32(sBp);
    const uint32_t* __restrict__ wbase = g_wBf + (size_t)e*NCHUNK*2048;

    uint2 pf[4];
    // ---- prologue: A chunk0 -> regs, B chunk0 -> sB stage0 via cp.async ----
    {
        const int off = -WP_ - 1;    // tap 0
        #pragma unroll
        for (int j = 0; j < 4; j++) {
            int m = m_row + j*32;
            pf[j] = *(const uint2*)(g_xh + (size_t)(s_pp[m] + off)*C_ + kq*4);
        }
        const uint4* bs = (const uint4*)wbase;
        #pragma unroll
        for (int j = 0; j < 2; j++)
            cp_async16(sB_byte + (tid + j*256)*16, bs + tid + j*256);
        CP_COMMIT();
    }

    for (int ch = 0; ch < NCHUNK; ch++) {
        const int st = ch & 1;
        uint32_t* sA = sAp + st*2048;
        uint32_t* sB = sBp + st*2048;

        // ---- STS A fragments from prefetched regs (already frag-order u32) ----
        {
            const int k0 = kq * 4;
            const int ks = k0 >> 4;
            const int la = ((k0 & 7) >> 1);
            const int rg_k = ((k0 >> 3) & 1) << 1;
            #pragma unroll
            for (int j = 0; j < 4; j++) {
                int m = m_row + j*32;
                int mt = m >> 4;
                int lane_a = ((m & 7) << 2) + la;
                int rg = ((m >> 3) & 1) + rg_k;
                int bi = ((ks*8 + mt)*32 + lane_a)*4 + rg;
                sA[bi]     = pf[j].x;   // (ci0, ci1)
                sA[bi + 4] = pf[j].y;   // (ci2, ci3)
            }
        }
        CP_WAIT0();          // B(ch) landed
        __syncthreads();     // sA[st] + sB[st] visible to all

        // ---- prefetch next chunk (overlaps mma below) ----
        if (ch + 1 < NCHUNK) {
            const int t = (ch+1) >> 2, ci0 = ((ch+1) & 3) * 32;
            const int off = (t/3 - 1)*WP_ + (t%3 - 1);
            #pragma unroll
            for (int j = 0; j < 4; j++) {
                int m = m_row + j*32;
                pf[j] = *(const uint2*)(g_xh + (size_t)(s_pp[m] + off)*C_ + ci0 + kq*4);
            }
            const uint4* bs = (const uint4*)(wbase + (size_t)(ch+1)*2048);
            const uint32_t dstb = sB_byte + (st^1)*8192;
            #pragma unroll
            for (int j = 0; j < 2; j++)
                cp_async16(dstb + (tid + j*256)*16, bs + tid + j*256);
            CP_COMMIT();
        }

        // ---- mma: single-pass fp16 ----
        #pragma unroll
        for (int ks = 0; ks < 2; ks++) {
            uint32_t bh[4][2];
            #pragma unroll
            for (int nt = 0; nt < 4; nt++) {
                int ng = wn*4 + nt;
                uint2 h2 = ((const uint2*)(sB + (ks*16 + ng)*64))[lane];
                bh[nt][0] = h2.x; bh[nt][1] = h2.y;
            }
            #pragma unroll
            for (int mt = 0; mt < 4; mt++) {
                int mg = wm*4 + mt;
                uint4 ah4 = ((const uint4*)(sA + (ks*8 + mg)*128))[lane];
                uint32_t ah[4] = {ah4.x, ah4.y, ah4.z, ah4.w};
                #pragma unroll
                for (int nt = 0; nt < 4; nt++)
                    mma_fp16(c[mt][nt], ah, bh[nt]);
            }
        }
        // no trailing sync: 2-stage rotation, single barrier per chunk.
    }

    // ---- epilogue: (acc + bias) * wt  ->  g_partial[slot][pid][co] ----
    #pragma unroll
    for (int mt = 0; mt < 4; mt++) {
        int r0 = wm*64 + mt*16 + (lane >> 2);
        #pragma unroll
        for (int half = 0; half < 2; half++) {
            int r = r0 + half*8;
            float wt = s_wt[r];
            if (wt != 0.f) {
                int pm  = s_pid[r];
                int pid = pm & 0xFFFFF;
                int slot = pm >> 20;
                float* dst = g_partial + ((size_t)slot*P_ + pid)*C_;
                #pragma unroll
                for (int nt = 0; nt < 4; nt++) {
                    int n0 = (wn*4 + nt)*8 + (lane & 3)*2;
                    float2 v;
                    v.x = (c[mt][nt][half*2 + 0] + s_bias[n0])     * wt;
                    v.y = (c[mt][nt][half*2 + 1] + s_bias[n0 + 1]) * wt;
                    *(float2*)(dst + n0) = v;
                }
            }
        }
    }
}

// ---------------- combine: out = p0 + p1 + p2 (transpose to NCHW) ---------
__global__ void k_combine(float* __restrict__ out) {
    __shared__ float t[32][33];
    int pid0 = blockIdx.x * 32, co0 = blockIdx.y * 32;
    int tid = threadIdx.x;
    #pragma unroll
    for (int r = 0; r < 4; r++) {
        int i = r*256 + tid;
        int pr = i >> 5, cl = i & 31;
        size_t o0 = ((size_t)(pid0 + pr))*C_ + co0 + cl;
        t[cl][pr] = g_partial[o0] + g_partial[(size_t)P_*C_ + o0]
                  + g_partial[2*(size_t)P_*C_ + o0];
    }
    __syncthreads();
    #pragma unroll
    for (int r = 0; r < 4; r++) {
        int i = r*256 + tid;
        int cl = i >> 5, pl = i & 31;
        int pid = pid0 + pl;
        int b = pid / HW_, hw = pid - b*HW_;
        out[((size_t)b*C_ + co0 + cl)*HW_ + hw] = t[cl][pl];
    }
}

// ---------------- launch ---------------------------------------------------
extern "C" void kernel_launch(void* const* d_in, const int* in_sizes, int n_in,
                              void* d_out, int out_size) {
    const float* x  = (const float*)d_in[0];
    const float* gw = (const float*)d_in[1];
    const float* gb = (const float*)d_in[2];
    const float* ew = (const float*)d_in[3];
    const float* eb = (const float*)d_in[4];
    const float* sw = (const float*)d_in[5];
    const float* sb = (const float*)d_in[6];
    float* out = (float*)d_out;

    cudaFuncSetAttribute(k_mma, cudaFuncAttributeMaxDynamicSharedMemorySize, 32768);

    k_prep<<<NB_PREP, 256>>>(x, ew, sw, eb, sb);
    k_gate<<<(P_ + 255)/256, 256>>>(x, gw, gb);
    k_mma<<<dim3(P_/128, NEX), 256, 32768>>>();
    k_combine<<<dim3(P_/32, C_/32), 256>>>(out);
}

// round 11
// speedup vs baseline: 1.4629x; 1.4629x over previous
#include <cuda_runtime.h>
#include <cuda_bf16.h>
#include <cuda_fp16.h>
#include <cstdint>

#define B_    4
#define C_    128
#define H_    96
#define W_    96
#define HW_   (H_*W_)          // 9216
#define P_    (B_*HW_)         // 36864
#define E_    8
#define NEX   9
#define WP_   98
#define HP_   98
#define HWP_  (HP_*WP_)        // 9604
#define PPAD_ (B_*HWP_)        // 38416
#define NCHUNK 36              // K=1152 in chunks of 32

// ---------------- device globals (no allocation) --------------------------
__device__ __half   g_xh[PPAD_*C_];            // fp16 NHWC padded activations (9.8MB)
__device__ uint32_t g_wBf[NEX*NCHUNK*2048];    // fp16 B frags: [e][chunk]     (2.6MB)
__device__ float    g_bias[NEX*C_];
__device__ int      g_count[E_];
__device__ unsigned long long g_list[E_][P_];  // (w_bits<<32)|(slot<<20)|pid
__device__ float    g_partial[3*P_*C_];        // [slot][pid][co]  (56.6MB)

// ---------------- helpers --------------------------------------------------
__device__ __forceinline__ void mma_fp16(float* c, const uint32_t* a, const uint32_t* b) {
    asm volatile(
        "mma.sync.aligned.m16n8k16.row.col.f32.f16.f16.f32 "
        "{%0,%1,%2,%3}, {%4,%5,%6,%7}, {%8,%9}, {%0,%1,%2,%3};"
        : "+f"(c[0]), "+f"(c[1]), "+f"(c[2]), "+f"(c[3])
        : "r"(a[0]), "r"(a[1]), "r"(a[2]), "r"(a[3]), "r"(b[0]), "r"(b[1]));
}

__device__ __forceinline__ uint32_t smem_u32(const void* p) {
    uint32_t a;
    asm("{ .reg .u64 t; cvta.to.shared.u64 t, %1; cvt.u32.u64 %0, t; }" : "=r"(a) : "l"(p));
    return a;
}
__device__ __forceinline__ void cp_async16(uint32_t dst, const void* src) {
    asm volatile("cp.async.cg.shared.global [%0], [%1], 16;" :: "r"(dst), "l"(src) : "memory");
}
#define CP_COMMIT() asm volatile("cp.async.commit_group;" ::: "memory")
#define CP_WAIT0()  asm volatile("cp.async.wait_group 0;" ::: "memory")

// ---------------- init: counters + zero ONLY the halo ring ----------------
// 4 b * 388 halo px * 32 uint2 (128 ci) = 49664 items
__global__ void k_init_halo() {
    int g = blockIdx.x * blockDim.x + threadIdx.x;
    if (g < E_ && blockIdx.x == 0) g_count[g] = 0;
    if (g >= 4*388*32) return;
    int ci8 = g & 31;
    int j   = (g >> 5) % 388;
    int b   = g / (388*32);
    int hp, wp;
    if (j < 98)        { hp = 0;  wp = j; }
    else if (j < 196)  { hp = 97; wp = j - 98; }
    else { int k = j - 196; hp = 1 + (k >> 1); wp = (k & 1) ? 97 : 0; }
    int pp = b*HWP_ + hp*WP_ + wp;
    ((uint2*)(g_xh + (size_t)pp*C_))[ci8] = make_uint2(0u, 0u);
}

// ---------------- NCHW fp32 -> NHWC fp16 padded (interior) ----------------
__global__ void k_nhwc(const float* __restrict__ x) {
    __shared__ float t[32][33];
    int hw0 = blockIdx.x * 32, ci0 = blockIdx.y * 32, b = blockIdx.z;
    int tid = threadIdx.x;
    #pragma unroll
    for (int r = 0; r < 4; r++) {
        int ci = (tid >> 5) + r*8, hw = tid & 31;
        t[ci][hw] = x[((b*C_) + ci0 + ci)*HW_ + hw0 + hw];
    }
    __syncthreads();
    #pragma unroll
    for (int r = 0; r < 4; r++) {
        int hwl = (tid >> 5) + r*8, cil = tid & 31;
        int hw = hw0 + hwl, h = hw / W_, w = hw - h*W_;
        int pad = b*HWP_ + (h+1)*WP_ + (w+1);
        g_xh[(size_t)pad*C_ + ci0 + cil] = __float2half_rn(t[cil][hwl]);
    }
}

// weights -> fp16 mma fragment order, packed per ci pair
__global__ void k_repackB(const float* __restrict__ ew, const float* __restrict__ sw,
                          const float* __restrict__ eb, const float* __restrict__ sb) {
    int idx = blockIdx.x * blockDim.x + threadIdx.x;
    const int total = NEX*C_*9*64;
    if (idx < total) {
        int cip = idx & 63;
        int tap = (idx >> 6) % 9;
        int co  = (idx / (64*9)) & 127;
        int e   = idx / (64*9*C_);
        int ci  = cip * 2;
        float v0, v1;
        if (e < 8) {
            int base = ((e*C_ + co)*C_ + ci)*9 + tap;
            v0 = ew[base]; v1 = ew[base + 9];
        } else {
            int base = (co*C_ + ci)*9 + tap;
            v0 = sw[base]; v1 = sw[base + 9];
        }
        uint32_t h0 = (uint32_t)__half_as_ushort(__float2half_rn(v0));
        uint32_t h1 = (uint32_t)__half_as_ushort(__float2half_rn(v1));
        int k_abs = tap*C_ + ci;
        int chunk = k_abs >> 5;
        int k0 = k_abs & 31;
        int ks = k0 >> 4;
        int lane = ((co & 7) << 2) + ((k0 & 7) >> 1);
        int reg  = (k0 >> 3) & 1;
        int nt   = co >> 3;
        size_t di = (size_t)(e*NCHUNK + chunk)*2048 + ((ks*16 + nt)*32 + lane)*2 + reg;
        g_wBf[di] = h0 | (h1 << 16);
    }
    if (idx < NEX*C_) {
        int ex = idx >> 7, co = idx & 127;
        g_bias[idx] = (ex < 8) ? eb[idx] : sb[co];
    }
}

// ---------------- gate: fp32 NCHW conv(8) + sigmoid + top2 + softmax ------
// MUST stay fp32 on the ORIGINAL x: expert selection is a decision boundary;
// fp16 inputs flip near-tied top-2 picks and blow up rel_err (R7 lesson).
__global__ void k_gate(const float* __restrict__ x, const float* __restrict__ gw,
                       const float* __restrict__ gbias) {
    __shared__ float sgw[E_*C_*9];
    for (int i = threadIdx.x; i < E_*C_*9; i += blockDim.x) sgw[i] = gw[i];
    __syncthreads();

    int pid = blockIdx.x * blockDim.x + threadIdx.x;
    if (pid >= P_) return;
    int b = pid / HW_, hw = pid - b*HW_;
    int h = hw / W_, w = hw - h*W_;
    const float* xb = x + (size_t)b*C_*HW_ + hw;
    bool hm = h > 0, hp = h < H_-1, wm = w > 0, wp = w < W_-1;

    float acc[E_];
    #pragma unroll
    for (int e = 0; e < E_; e++) acc[e] = 0.f;
    for (int ci = 0; ci < C_; ci++) {
        const float* xp = xb + ci*HW_;
        float xv[9];
        xv[0] = (hm && wm) ? xp[-W_-1] : 0.f;
        xv[1] =  hm        ? xp[-W_]   : 0.f;
        xv[2] = (hm && wp) ? xp[-W_+1] : 0.f;
        xv[3] =  wm        ? xp[-1]    : 0.f;
        xv[4] =              xp[0];
        xv[5] =  wp        ? xp[1]     : 0.f;
        xv[6] = (hp && wm) ? xp[W_-1]  : 0.f;
        xv[7] =  hp        ? xp[W_]    : 0.f;
        xv[8] = (hp && wp) ? xp[W_+1]  : 0.f;
        #pragma unroll
        for (int e = 0; e < E_; e++) {
            const float* wp9 = &sgw[(e*C_ + ci)*9];
            float a = acc[e];
            #pragma unroll
            for (int t = 0; t < 9; t++) a = fmaf(xv[t], wp9[t], a);
            acc[e] = a;
        }
    }
    float s[E_], bsc[E_];
    #pragma unroll
    for (int e = 0; e < E_; e++) {
        s[e]   = 1.f / (1.f + expf(-acc[e]));
        bsc[e] = s[e] + gbias[e];
    }
    int e0 = 0;
    #pragma unroll
    for (int e = 1; e < E_; e++) if (bsc[e] > bsc[e0]) e0 = e;
    int e1 = (e0 == 0) ? 1 : 0;
    #pragma unroll
    for (int e = 0; e < E_; e++) if (e != e0 && bsc[e] > bsc[e1]) e1 = e;
    float m = fmaxf(s[e0], s[e1]);
    float d0 = expf(s[e0]-m), d1 = expf(s[e1]-m);
    float inv = 1.f / (d0 + d1);
    int p0 = atomicAdd(&g_count[e0], 1);
    g_list[e0][p0] = (((unsigned long long)__float_as_uint(d0*inv)) << 32) | (unsigned)pid;
    int p1 = atomicAdd(&g_count[e1], 1);
    g_list[e1][p1] = (((unsigned long long)__float_as_uint(d1*inv)) << 32) | (unsigned)(pid | (1u<<20));
}

// ---------------- fp16 mma.sync expert GEMM (pipelined, single-pass) ------
// CTA: 128 pixels x 128 couts, one expert. 8 warps in 2(M)x4(N).
__global__ __launch_bounds__(256, 2)
void k_mma() {
    const int e    = blockIdx.y;
    const int tile = blockIdx.x;
    const int n    = (e < 8) ? g_count[e] : P_;
    if (tile * 128 >= n) return;

    extern __shared__ uint32_t dsm[];
    uint32_t* sAp = dsm;          // 2 stages x 2048 u32
    uint32_t* sBp = dsm + 4096;   // 2 stages x 2048 u32
    __shared__ int   s_pid[128];
    __shared__ int   s_pp[128];
    __shared__ float s_wt[128];
    __shared__ float s_bias[128];

    const int tid = threadIdx.x;
    if (tid < 128) {
        int idx = tile*128 + tid;
        int pid = 0, slot = 0; float wt = 0.f;
        if (e < 8) {
            if (idx < n) {
                unsigned long long v = g_list[e][idx];
                wt   = __uint_as_float((unsigned)(v >> 32));
                unsigned lo = (unsigned)v;
                pid  = lo & 0xFFFFF;
                slot = (lo >> 20) & 1;
            }
        } else { pid = idx; wt = 1.f; slot = 2; }
        int b = pid / HW_, hw = pid - b*HW_;
        int h = hw / W_, w = hw - h*W_;
        s_pp[tid]   = (wt != 0.f) ? (b*HWP_ + (h+1)*WP_ + (w+1)) : (WP_ + 1);
        s_pid[tid]  = pid | (slot << 20);
        s_wt[tid]   = wt;
        s_bias[tid] = g_bias[e*C_ + tid];
    }
    __syncthreads();

    const int lane = tid & 31, wid = tid >> 5;
    const int wm = wid >> 2, wn = wid & 3;

    float c[4][4][4];
    #pragma unroll
    for (int i = 0; i < 4; i++)
        #pragma unroll
        for (int j = 0; j < 4; j++)
            #pragma unroll
            for (int k = 0; k < 4; k++) c[i][j][k] = 0.f;

    const int m_row = tid >> 3;      // A gather: 8 threads per pixel row
    const int kq    = tid & 7;       // each covers 4 ci (8 bytes fp16)
    const uint32_t sB_byte = smem_u32(sBp);
    const uint32_t* __restrict__ wbase = g_wBf + (size_t)e*NCHUNK*2048;

    uint2 pf[4];
    // ---- prologue: A chunk0 -> regs, B chunk0 -> sB stage0 via cp.async ----
    {
        const int off = -WP_ - 1;    // tap 0
        #pragma unroll
        for (int j = 0; j < 4; j++) {
            int m = m_row + j*32;
            pf[j] = *(const uint2*)(g_xh + (size_t)(s_pp[m] + off)*C_ + kq*4);
        }
        const uint4* bs = (const uint4*)wbase;
        #pragma unroll
        for (int j = 0; j < 2; j++)
            cp_async16(sB_byte + (tid + j*256)*16, bs + tid + j*256);
        CP_COMMIT();
    }

    for (int ch = 0; ch < NCHUNK; ch++) {
        const int st = ch & 1;
        uint32_t* sA = sAp + st*2048;
        uint32_t* sB = sBp + st*2048;

        // ---- STS A fragments from prefetched regs (already frag-order u32) ----
        {
            const int k0 = kq * 4;
            const int ks = k0 >> 4;
            const int la = ((k0 & 7) >> 1);
            const int rg_k = ((k0 >> 3) & 1) << 1;
            #pragma unroll
            for (int j = 0; j < 4; j++) {
                int m = m_row + j*32;
                int mt = m >> 4;
                int lane_a = ((m & 7) << 2) + la;
                int rg = ((m >> 3) & 1) + rg_k;
                int bi = ((ks*8 + mt)*32 + lane_a)*4 + rg;
                sA[bi]     = pf[j].x;   // (ci0, ci1)
                sA[bi + 4] = pf[j].y;   // (ci2, ci3)
            }
        }
        CP_WAIT0();          // B(ch) landed
        __syncthreads();     // sA[st] + sB[st] visible to all

        // ---- prefetch next chunk (overlaps mma below) ----
        if (ch + 1 < NCHUNK) {
            const int t = (ch+1) >> 2, ci0 = ((ch+1) & 3) * 32;
            const int off = (t/3 - 1)*WP_ + (t%3 - 1);
            #pragma unroll
            for (int j = 0; j < 4; j++) {
                int m = m_row + j*32;
                pf[j] = *(const uint2*)(g_xh + (size_t)(s_pp[m] + off)*C_ + ci0 + kq*4);
            }
            const uint4* bs = (const uint4*)(wbase + (size_t)(ch+1)*2048);
            const uint32_t dstb = sB_byte + (st^1)*8192;
            #pragma unroll
            for (int j = 0; j < 2; j++)
                cp_async16(dstb + (tid + j*256)*16, bs + tid + j*256);
            CP_COMMIT();
        }

        // ---- mma: single-pass fp16 ----
        #pragma unroll
        for (int ks = 0; ks < 2; ks++) {
            uint32_t bh[4][2];
            #pragma unroll
            for (int nt = 0; nt < 4; nt++) {
                int ng = wn*4 + nt;
                uint2 h2 = ((const uint2*)(sB + (ks*16 + ng)*64))[lane];
                bh[nt][0] = h2.x; bh[nt][1] = h2.y;
            }
            #pragma unroll
            for (int mt = 0; mt < 4; mt++) {
                int mg = wm*4 + mt;
                uint4 ah4 = ((const uint4*)(sA + (ks*8 + mg)*128))[lane];
                uint32_t ah[4] = {ah4.x, ah4.y, ah4.z, ah4.w};
                #pragma unroll
                for (int nt = 0; nt < 4; nt++)
                    mma_fp16(c[mt][nt], ah, bh[nt]);
            }
        }
        // no trailing sync: 2-stage rotation, single barrier per chunk.
    }

    // ---- epilogue: (acc + bias) * wt  ->  g_partial[slot][pid][co] ----
    #pragma unroll
    for (int mt = 0; mt < 4; mt++) {
        int r0 = wm*64 + mt*16 + (lane >> 2);
        #pragma unroll
        for (int half = 0; half < 2; half++) {
            int r = r0 + half*8;
            float wt = s_wt[r];
            if (wt != 0.f) {
                int pm  = s_pid[r];
                int pid = pm & 0xFFFFF;
                int slot = pm >> 20;
                float* dst = g_partial + ((size_t)slot*P_ + pid)*C_;
                #pragma unroll
                for (int nt = 0; nt < 4; nt++) {
                    int n0 = (wn*4 + nt)*8 + (lane & 3)*2;
                    float2 v;
                    v.x = (c[mt][nt][half*2 + 0] + s_bias[n0])     * wt;
                    v.y = (c[mt][nt][half*2 + 1] + s_bias[n0 + 1]) * wt;
                    *(float2*)(dst + n0) = v;
                }
            }
        }
    }
}

// ---------------- combine: out = p0 + p1 + p2 (transpose to NCHW) ---------
__global__ void k_combine(float* __restrict__ out) {
    __shared__ float t[32][33];
    int pid0 = blockIdx.x * 32, co0 = blockIdx.y * 32;
    int tid = threadIdx.x;
    #pragma unroll
    for (int r = 0; r < 4; r++) {
        int i = r*256 + tid;
        int pr = i >> 5, cl = i & 31;
        size_t o0 = ((size_t)(pid0 + pr))*C_ + co0 + cl;
        t[cl][pr] = g_partial[o0] + g_partial[(size_t)P_*C_ + o0]
                  + g_partial[2*(size_t)P_*C_ + o0];
    }
    __syncthreads();
    #pragma unroll
    for (int r = 0; r < 4; r++) {
        int i = r*256 + tid;
        int cl = i >> 5, pl = i & 31;
        int pid = pid0 + pl;
        int b = pid / HW_, hw = pid - b*HW_;
        out[((size_t)b*C_ + co0 + cl)*HW_ + hw] = t[cl][pl];
    }
}

// ---------------- launch ---------------------------------------------------
extern "C" void kernel_launch(void* const* d_in, const int* in_sizes, int n_in,
                              void* d_out, int out_size) {
    const float* x  = (const float*)d_in[0];
    const float* gw = (const float*)d_in[1];
    const float* gb = (const float*)d_in[2];
    const float* ew = (const float*)d_in[3];
    const float* eb = (const float*)d_in[4];
    const float* sw = (const float*)d_in[5];
    const float* sb = (const float*)d_in[6];
    float* out = (float*)d_out;

    cudaFuncSetAttribute(k_mma, cudaFuncAttributeMaxDynamicSharedMemorySize, 32768);

    k_init_halo<<<(4*388*32 + 255)/256, 256>>>();
    k_nhwc<<<dim3(HW_/32, C_/32, B_), 256>>>(x);
    k_repackB<<<(NEX*C_*9*64 + 255)/256, 256>>>(ew, sw, eb, sb);
    k_gate<<<(P_ + 255)/256, 256>>>(x, gw, gb);
    k_mma<<<dim3(P_/128, NEX), 256, 32768>>>();
    k_combine<<<dim3(P_/32, C_/32), 256>>>(out);
}

// round 13
// speedup vs baseline: 1.5034x; 1.0277x over previous
#include <cuda_runtime.h>
#include <cuda_bf16.h>
#include <cuda_fp16.h>
#include <cstdint>

#define B_    4
#define C_    128
#define H_    96
#define W_    96
#define HW_   (H_*W_)          // 9216
#define P_    (B_*HW_)         // 36864
#define E_    8
#define NEX   9
#define WP_   98
#define HP_   98
#define HWP_  (HP_*WP_)        // 9604
#define PPAD_ (B_*HWP_)        // 38416
#define NCHUNK 36              // K=1152 in chunks of 32

// ---------------- device globals (no allocation) --------------------------
__device__ __half   g_xh[PPAD_*C_];            // fp16 NHWC padded activations (9.8MB)
__device__ uint32_t g_wBf[NEX*NCHUNK*2048];    // fp16 B frags: [e][chunk]     (2.6MB)
__device__ float    g_bias[NEX*C_];
__device__ int      g_count[E_];
__device__ unsigned long long g_list[E_][P_];  // (w_bits<<32)|(slot<<20)|pid
__device__ float    g_partial[3*P_*C_];        // [slot][pid][co]  (56.6MB)

// ---------------- helpers --------------------------------------------------
__device__ __forceinline__ void mma_fp16(float* c, const uint32_t* a, const uint32_t* b) {
    asm volatile(
        "mma.sync.aligned.m16n8k16.row.col.f32.f16.f16.f32 "
        "{%0,%1,%2,%3}, {%4,%5,%6,%7}, {%8,%9}, {%0,%1,%2,%3};"
        : "+f"(c[0]), "+f"(c[1]), "+f"(c[2]), "+f"(c[3])
        : "r"(a[0]), "r"(a[1]), "r"(a[2]), "r"(a[3]), "r"(b[0]), "r"(b[1]));
}

__device__ __forceinline__ uint32_t smem_u32(const void* p) {
    uint32_t a;
    asm("{ .reg .u64 t; cvta.to.shared.u64 t, %1; cvt.u32.u64 %0, t; }" : "=r"(a) : "l"(p));
    return a;
}
__device__ __forceinline__ void cp_async16(uint32_t dst, const void* src) {
    asm volatile("cp.async.cg.shared.global [%0], [%1], 16;" :: "r"(dst), "l"(src) : "memory");
}
#define CP_COMMIT() asm volatile("cp.async.commit_group;" ::: "memory")
#define CP_WAIT0()  asm volatile("cp.async.wait_group 0;" ::: "memory")

// ---------------- init: counters + zero ONLY the halo ring ----------------
// 4 b * 388 halo px * 32 uint2 (128 ci) = 49664 items
__global__ void k_init_halo() {
    int g = blockIdx.x * blockDim.x + threadIdx.x;
    if (g < E_ && blockIdx.x == 0) g_count[g] = 0;
    if (g >= 4*388*32) return;
    int ci8 = g & 31;
    int j   = (g >> 5) % 388;
    int b   = g / (388*32);
    int hp, wp;
    if (j < 98)        { hp = 0;  wp = j; }
    else if (j < 196)  { hp = 97; wp = j - 98; }
    else { int k = j - 196; hp = 1 + (k >> 1); wp = (k & 1) ? 97 : 0; }
    int pp = b*HWP_ + hp*WP_ + wp;
    ((uint2*)(g_xh + (size_t)pp*C_))[ci8] = make_uint2(0u, 0u);
}

// ---------------- NCHW fp32 -> NHWC fp16 padded (interior) ----------------
__global__ void k_nhwc(const float* __restrict__ x) {
    __shared__ float t[32][33];
    int hw0 = blockIdx.x * 32, ci0 = blockIdx.y * 32, b = blockIdx.z;
    int tid = threadIdx.x;
    #pragma unroll
    for (int r = 0; r < 4; r++) {
        int ci = (tid >> 5) + r*8, hw = tid & 31;
        t[ci][hw] = x[((b*C_) + ci0 + ci)*HW_ + hw0 + hw];
    }
    __syncthreads();
    #pragma unroll
    for (int r = 0; r < 4; r++) {
        int hwl = (tid >> 5) + r*8, cil = tid & 31;
        int hw = hw0 + hwl, h = hw / W_, w = hw - h*W_;
        int pad = b*HWP_ + (h+1)*WP_ + (w+1);
        g_xh[(size_t)pad*C_ + ci0 + cil] = __float2half_rn(t[cil][hwl]);
    }
}

// weights -> fp16 mma fragment order, packed per ci pair
__global__ void k_repackB(const float* __restrict__ ew, const float* __restrict__ sw,
                          const float* __restrict__ eb, const float* __restrict__ sb) {
    int idx = blockIdx.x * blockDim.x + threadIdx.x;
    const int total = NEX*C_*9*64;
    if (idx < total) {
        int cip = idx & 63;
        int tap = (idx >> 6) % 9;
        int co  = (idx / (64*9)) & 127;
        int e   = idx / (64*9*C_);
        int ci  = cip * 2;
        float v0, v1;
        if (e < 8) {
            int base = ((e*C_ + co)*C_ + ci)*9 + tap;
            v0 = ew[base]; v1 = ew[base + 9];
        } else {
            int base = (co*C_ + ci)*9 + tap;
            v0 = sw[base]; v1 = sw[base + 9];
        }
        uint32_t h0 = (uint32_t)__half_as_ushort(__float2half_rn(v0));
        uint32_t h1 = (uint32_t)__half_as_ushort(__float2half_rn(v1));
        int k_abs = tap*C_ + ci;
        int chunk = k_abs >> 5;
        int k0 = k_abs & 31;
        int ks = k0 >> 4;
        int lane = ((co & 7) << 2) + ((k0 & 7) >> 1);
        int reg  = (k0 >> 3) & 1;
        int nt   = co >> 3;
        size_t di = (size_t)(e*NCHUNK + chunk)*2048 + ((ks*16 + nt)*32 + lane)*2 + reg;
        g_wBf[di] = h0 | (h1 << 16);
    }
    if (idx < NEX*C_) {
        int ex = idx >> 7, co = idx & 127;
        g_bias[idx] = (ex < 8) ? eb[idx] : sb[co];
    }
}

// ---------------- gate: fp32 NCHW conv(8), 4 threads/pixel ----------------
// Routing MUST stay fp32 on the ORIGINAL x (R7 lesson: fp16 flips top-2).
// kq = tid&3 handles ci = 4*cl + kq; butterfly reduce over kq.
// smem weights [ci][e][tap] (stride 72 words): the 4 kq lanes hit banks
// +0/+8/+16/+24 -> conflict-free; broadcast across pixel lanes.
__global__ __launch_bounds__(256, 6)
void k_gate(const float* __restrict__ x, const float* __restrict__ gw,
            const float* __restrict__ gbias) {
    __shared__ float sgw[C_*72];   // [ci][e][tap]  36 KB
    const int tid = threadIdx.x;
    for (int i = tid; i < C_*72; i += 256) {
        int t = i % 9, e = (i / 9) & 7, ci = i / 72;
        sgw[i] = gw[(e*C_ + ci)*9 + t];
    }
    __syncthreads();

    const int kq = tid & 3;
    const int pg = tid >> 2;               // 0..63 pixels per block
    const int pid = blockIdx.x*64 + pg;
    int b = pid / HW_, hw = pid - b*HW_;
    int h = hw / W_, w = hw - h*W_;
    const float* xb = x + (size_t)b*C_*HW_ + hw;
    bool hm = h > 0, hp = h < H_-1, wm = w > 0, wp = w < W_-1;

    float acc[E_];
    #pragma unroll
    for (int e = 0; e < E_; e++) acc[e] = 0.f;

    #pragma unroll 4
    for (int cl = 0; cl < 32; cl++) {
        const int ci = cl*4 + kq;
        const float* xp = xb + ci*HW_;
        float xv[9];
        xv[0] = (hm && wm) ? xp[-W_-1] : 0.f;
        xv[1] =  hm        ? xp[-W_]   : 0.f;
        xv[2] = (hm && wp) ? xp[-W_+1] : 0.f;
        xv[3] =  wm        ? xp[-1]    : 0.f;
        xv[4] =              xp[0];
        xv[5] =  wp        ? xp[1]     : 0.f;
        xv[6] = (hp && wm) ? xp[W_-1]  : 0.f;
        xv[7] =  hp        ? xp[W_]    : 0.f;
        xv[8] = (hp && wp) ? xp[W_+1]  : 0.f;
        const float* wb = &sgw[ci*72];
        #pragma unroll
        for (int e = 0; e < E_; e++) {
            const float* w9 = wb + e*9;
            float a = acc[e];
            #pragma unroll
            for (int t = 0; t < 9; t++) a = fmaf(xv[t], w9[t], a);
            acc[e] = a;
        }
    }
    // reduce the 4 ci-partials (kq in lane bits 0..1)
    #pragma unroll
    for (int e = 0; e < E_; e++) {
        acc[e] += __shfl_xor_sync(0xFFFFFFFFu, acc[e], 1);
        acc[e] += __shfl_xor_sync(0xFFFFFFFFu, acc[e], 2);
    }

    if (kq == 0) {
        float s[E_], bsc[E_];
        #pragma unroll
        for (int e = 0; e < E_; e++) {
            s[e]   = 1.f / (1.f + expf(-acc[e]));
            bsc[e] = s[e] + gbias[e];
        }
        int e0 = 0;
        #pragma unroll
        for (int e = 1; e < E_; e++) if (bsc[e] > bsc[e0]) e0 = e;
        int e1 = (e0 == 0) ? 1 : 0;
        #pragma unroll
        for (int e = 0; e < E_; e++) if (e != e0 && bsc[e] > bsc[e1]) e1 = e;
        float m = fmaxf(s[e0], s[e1]);
        float d0 = expf(s[e0]-m), d1 = expf(s[e1]-m);
        float inv = 1.f / (d0 + d1);
        int p0 = atomicAdd(&g_count[e0], 1);
        g_list[e0][p0] = (((unsigned long long)__float_as_uint(d0*inv)) << 32) | (unsigned)pid;
        int p1 = atomicAdd(&g_count[e1], 1);
        g_list[e1][p1] = (((unsigned long long)__float_as_uint(d1*inv)) << 32) | (unsigned)(pid | (1u<<20));
    }
}

// ---------------- fp16 mma.sync expert GEMM (pipelined, single-pass) ------
// CTA: 128 pixels x 128 couts, one expert. 8 warps in 2(M)x4(N).
__global__ __launch_bounds__(256, 2)
void k_mma() {
    const int e    = blockIdx.y;
    const int tile = blockIdx.x;
    const int n    = (e < 8) ? g_count[e] : P_;
    if (tile * 128 >= n) return;

    extern __shared__ uint32_t dsm[];
    uint32_t* sAp = dsm;          // 2 stages x 2048 u32
    uint32_t* sBp = dsm + 4096;   // 2 stages x 2048 u32
    __shared__ int   s_pid[128];
    __shared__ int   s_pp[128];
    __shared__ float s_wt[128];
    __shared__ float s_bias[128];

    const int tid = threadIdx.x;
    if (tid < 128) {
        int idx = tile*128 + tid;
        int pid = 0, slot = 0; float wt = 0.f;
        if (e < 8) {
            if (idx < n) {
                unsigned long long v = g_list[e][idx];
                wt   = __uint_as_float((unsigned)(v >> 32));
                unsigned lo = (unsigned)v;
                pid  = lo & 0xFFFFF;
                slot = (lo >> 20) & 1;
            }
        } else { pid = idx; wt = 1.f; slot = 2; }
        int b = pid / HW_, hw = pid - b*HW_;
        int h = hw / W_, w = hw - h*W_;
        s_pp[tid]   = (wt != 0.f) ? (b*HWP_ + (h+1)*WP_ + (w+1)) : (WP_ + 1);
        s_pid[tid]  = pid | (slot << 20);
        s_wt[tid]   = wt;
        s_bias[tid] = g_bias[e*C_ + tid];
    }
    __syncthreads();

    const int lane = tid & 31, wid = tid >> 5;
    const int wm = wid >> 2, wn = wid & 3;

    float c[4][4][4];
    #pragma unroll
    for (int i = 0; i < 4; i++)
        #pragma unroll
        for (int j = 0; j < 4; j++)
            #pragma unroll
            for (int k = 0; k < 4; k++) c[i][j][k] = 0.f;

    const int m_row = tid >> 3;      // A gather: 8 threads per pixel row
    const int kq    = tid & 7;       // each covers 4 ci (8 bytes fp16)
    const uint32_t sB_byte = smem_u32(sBp);
    const uint32_t* __restrict__ wbase = g_wBf + (size_t)e*NCHUNK*2048;

    uint2 pf[4];
    // ---- prologue: A chunk0 -> regs, B chunk0 -> sB stage0 via cp.async ----
    {
        const int off = -WP_ - 1;    // tap 0
        #pragma unroll
        for (int j = 0; j < 4; j++) {
            int m = m_row + j*32;
            pf[j] = *(const uint2*)(g_xh + (size_t)(s_pp[m] + off)*C_ + kq*4);
        }
        const uint4* bs = (const uint4*)wbase;
        #pragma unroll
        for (int j = 0; j < 2; j++)
            cp_async16(sB_byte + (tid + j*256)*16, bs + tid + j*256);
        CP_COMMIT();
    }

    for (int ch = 0; ch < NCHUNK; ch++) {
        const int st = ch & 1;
        uint32_t* sA = sAp + st*2048;
        uint32_t* sB = sBp + st*2048;

        // ---- STS A fragments from prefetched regs (already frag-order u32) ----
        {
            const int k0 = kq * 4;
            const int ks = k0 >> 4;
            const int la = ((k0 & 7) >> 1);
            const int rg_k = ((k0 >> 3) & 1) << 1;
            #pragma unroll
            for (int j = 0; j < 4; j++) {
                int m = m_row + j*32;
                int mt = m >> 4;
                int lane_a = ((m & 7) << 2) + la;
                int rg = ((m >> 3) & 1) + rg_k;
                int bi = ((ks*8 + mt)*32 + lane_a)*4 + rg;
                sA[bi]     = pf[j].x;   // (ci0, ci1)
                sA[bi + 4] = pf[j].y;   // (ci2, ci3)
            }
        }
        CP_WAIT0();          // B(ch) landed
        __syncthreads();     // sA[st] + sB[st] visible to all

        // ---- prefetch next chunk (overlaps mma below) ----
        if (ch + 1 < NCHUNK) {
            const int t = (ch+1) >> 2, ci0 = ((ch+1) & 3) * 32;
            const int off = (t/3 - 1)*WP_ + (t%3 - 1);
            #pragma unroll
            for (int j = 0; j < 4; j++) {
                int m = m_row + j*32;
                pf[j] = *(const uint2*)(g_xh + (size_t)(s_pp[m] + off)*C_ + ci0 + kq*4);
            }
            const uint4* bs = (const uint4*)(wbase + (size_t)(ch+1)*2048);
            const uint32_t dstb = sB_byte + (st^1)*8192;
            #pragma unroll
            for (int j = 0; j < 2; j++)
                cp_async16(dstb + (tid + j*256)*16, bs + tid + j*256);
            CP_COMMIT();
        }

        // ---- mma: single-pass fp16 ----
        #pragma unroll
        for (int ks = 0; ks < 2; ks++) {
            uint32_t bh[4][2];
            #pragma unroll
            for (int nt = 0; nt < 4; nt++) {
                int ng = wn*4 + nt;
                uint2 h2 = ((const uint2*)(sB + (ks*16 + ng)*64))[lane];
                bh[nt][0] = h2.x; bh[nt][1] = h2.y;
            }
            #pragma unroll
            for (int mt = 0; mt < 4; mt++) {
                int mg = wm*4 + mt;
                uint4 ah4 = ((const uint4*)(sA + (ks*8 + mg)*128))[lane];
                uint32_t ah[4] = {ah4.x, ah4.y, ah4.z, ah4.w};
                #pragma unroll
                for (int nt = 0; nt < 4; nt++)
                    mma_fp16(c[mt][nt], ah, bh[nt]);
            }
        }
        // no trailing sync: 2-stage rotation, single barrier per chunk.
    }

    // ---- epilogue: (acc + bias) * wt  ->  g_partial[slot][pid][co] ----
    #pragma unroll
    for (int mt = 0; mt < 4; mt++) {
        int r0 = wm*64 + mt*16 + (lane >> 2);
        #pragma unroll
        for (int half = 0; half < 2; half++) {
            int r = r0 + half*8;
            float wt = s_wt[r];
            if (wt != 0.f) {
                int pm  = s_pid[r];
                int pid = pm & 0xFFFFF;
                int slot = pm >> 20;
                float* dst = g_partial + ((size_t)slot*P_ + pid)*C_;
                #pragma unroll
                for (int nt = 0; nt < 4; nt++) {
                    int n0 = (wn*4 + nt)*8 + (lane & 3)*2;
                    float2 v;
                    v.x = (c[mt][nt][half*2 + 0] + s_bias[n0])     * wt;
                    v.y = (c[mt][nt][half*2 + 1] + s_bias[n0 + 1]) * wt;
                    *(float2*)(dst + n0) = v;
                }
            }
        }
    }
}

// ---------------- combine: out = p0 + p1 + p2 (transpose to NCHW) ---------
__global__ void k_combine(float* __restrict__ out) {
    __shared__ float t[32][33];
    int pid0 = blockIdx.x * 32, co0 = blockIdx.y * 32;
    int tid = threadIdx.x;
    #pragma unroll
    for (int r = 0; r < 4; r++) {
        int i = r*256 + tid;
        int pr = i >> 5, cl = i & 31;
        size_t o0 = ((size_t)(pid0 + pr))*C_ + co0 + cl;
        t[cl][pr] = g_partial[o0] + g_partial[(size_t)P_*C_ + o0]
                  + g_partial[2*(size_t)P_*C_ + o0];
    }
    __syncthreads();
    #pragma unroll
    for (int r = 0; r < 4; r++) {
        int i = r*256 + tid;
        int cl = i >> 5, pl = i & 31;
        int pid = pid0 + pl;
        int b = pid / HW_, hw = pid - b*HW_;
        out[((size_t)b*C_ + co0 + cl)*HW_ + hw] = t[cl][pl];
    }
}

// ---------------- launch ---------------------------------------------------
extern "C" void kernel_launch(void* const* d_in, const int* in_sizes, int n_in,
                              void* d_out, int out_size) {
    const float* x  = (const float*)d_in[0];
    const float* gw = (const float*)d_in[1];
    const float* gb = (const float*)d_in[2];
    const float* ew = (const float*)d_in[3];
    const float* eb = (const float*)d_in[4];
    const float* sw = (const float*)d_in[5];
    const float* sb = (const float*)d_in[6];
    float* out = (float*)d_out;

    cudaFuncSetAttribute(k_mma, cudaFuncAttributeMaxDynamicSharedMemorySize, 32768);

    k_init_halo<<<(4*388*32 + 255)/256, 256>>>();
    k_nhwc<<<dim3(HW_/32, C_/32, B_), 256>>>(x);
    k_repackB<<<(NEX*C_*9*64 + 255)/256, 256>>>(ew, sw, eb, sb);
    k_gate<<<P_/64, 256>>>(x, gw, gb);
    k_mma<<<dim3(P_/128, NEX), 256, 32768>>>();
    k_combine<<<dim3(P_/32, C_/32), 256>>>(out);
}

// round 15
// speedup vs baseline: 1.6639x; 1.1067x over previous
#include <cuda_runtime.h>
#include <cuda_bf16.h>
#include <cuda_fp16.h>
#include <cstdint>

#define B_    4
#define C_    128
#define H_    96
#define W_    96
#define HW_   (H_*W_)          // 9216
#define P_    (B_*HW_)         // 36864
#define E_    8
#define NEX   9
#define WP_   98
#define HP_   98
#define HWP_  (HP_*WP_)        // 9604
#define PPAD_ (B_*HWP_)        // 38416
#define NCHUNK 36              // K=1152 in chunks of 32

// ---------------- device globals (no allocation) --------------------------
__device__ __half   g_xh[PPAD_*C_];            // fp16 NHWC padded activations (9.8MB)
__device__ uint32_t g_wBf[NEX*NCHUNK*2048];    // fp16 B frags: [e][chunk]     (2.6MB)
__device__ float    g_wG[C_*9*E_];             // gate weights [ci][tap][e] (36KB)
__device__ float    g_bias[NEX*C_];
__device__ int      g_count[E_];
__device__ unsigned long long g_list[E_][P_];  // (w_bits<<32)|(slot<<20)|pid
__device__ float    g_partial[3*P_*C_];        // [slot][pid][co]  (56.6MB)

// ---------------- helpers --------------------------------------------------
__device__ __forceinline__ void mma_fp16(float* c, const uint32_t* a, const uint32_t* b) {
    asm volatile(
        "mma.sync.aligned.m16n8k16.row.col.f32.f16.f16.f32 "
        "{%0,%1,%2,%3}, {%4,%5,%6,%7}, {%8,%9}, {%0,%1,%2,%3};"
        : "+f"(c[0]), "+f"(c[1]), "+f"(c[2]), "+f"(c[3])
        : "r"(a[0]), "r"(a[1]), "r"(a[2]), "r"(a[3]), "r"(b[0]), "r"(b[1]));
}

__device__ __forceinline__ uint32_t smem_u32(const void* p) {
    uint32_t a;
    asm("{ .reg .u64 t; cvta.to.shared.u64 t, %1; cvt.u32.u64 %0, t; }" : "=r"(a) : "l"(p));
    return a;
}
__device__ __forceinline__ void cp_async16(uint32_t dst, const void* src) {
    asm volatile("cp.async.cg.shared.global [%0], [%1], 16;" :: "r"(dst), "l"(src) : "memory");
}
#define CP_COMMIT() asm volatile("cp.async.commit_group;" ::: "memory")
#define CP_WAIT0()  asm volatile("cp.async.wait_group 0;" ::: "memory")

// ---------------- init: counters + zero ONLY the halo ring ----------------
// 4 b * 388 halo px * 32 uint2 (128 ci) = 49664 items
__global__ void k_init_halo() {
    int g = blockIdx.x * blockDim.x + threadIdx.x;
    if (g < E_ && blockIdx.x == 0) g_count[g] = 0;
    if (g >= 4*388*32) return;
    int ci8 = g & 31;
    int j   = (g >> 5) % 388;
    int b   = g / (388*32);
    int hp, wp;
    if (j < 98)        { hp = 0;  wp = j; }
    else if (j < 196)  { hp = 97; wp = j - 98; }
    else { int k = j - 196; hp = 1 + (k >> 1); wp = (k & 1) ? 97 : 0; }
    int pp = b*HWP_ + hp*WP_ + wp;
    ((uint2*)(g_xh + (size_t)pp*C_))[ci8] = make_uint2(0u, 0u);
}

// ---------------- NCHW fp32 -> NHWC fp16 padded (interior) ----------------
__global__ void k_nhwc(const float* __restrict__ x) {
    __shared__ float t[32][33];
    int hw0 = blockIdx.x * 32, ci0 = blockIdx.y * 32, b = blockIdx.z;
    int tid = threadIdx.x;
    #pragma unroll
    for (int r = 0; r < 4; r++) {
        int ci = (tid >> 5) + r*8, hw = tid & 31;
        t[ci][hw] = x[((b*C_) + ci0 + ci)*HW_ + hw0 + hw];
    }
    __syncthreads();
    #pragma unroll
    for (int r = 0; r < 4; r++) {
        int hwl = (tid >> 5) + r*8, cil = tid & 31;
        int hw = hw0 + hwl, h = hw / W_, w = hw - h*W_;
        int pad = b*HWP_ + (h+1)*WP_ + (w+1);
        g_xh[(size_t)pad*C_ + ci0 + cil] = __float2half_rn(t[cil][hwl]);
    }
}

// weights -> fp16 mma fragment order + gate weights [ci][tap][e] ----------
__global__ void k_repackB(const float* __restrict__ ew, const float* __restrict__ sw,
                          const float* __restrict__ eb, const float* __restrict__ sb,
                          const float* __restrict__ gw) {
    int idx = blockIdx.x * blockDim.x + threadIdx.x;
    const int total = NEX*C_*9*64;
    if (idx < total) {
        int cip = idx & 63;
        int tap = (idx >> 6) % 9;
        int co  = (idx / (64*9)) & 127;
        int e   = idx / (64*9*C_);
        int ci  = cip * 2;
        float v0, v1;
        if (e < 8) {
            int base = ((e*C_ + co)*C_ + ci)*9 + tap;
            v0 = ew[base]; v1 = ew[base + 9];
        } else {
            int base = (co*C_ + ci)*9 + tap;
            v0 = sw[base]; v1 = sw[base + 9];
        }
        uint32_t h0 = (uint32_t)__half_as_ushort(__float2half_rn(v0));
        uint32_t h1 = (uint32_t)__half_as_ushort(__float2half_rn(v1));
        int k_abs = tap*C_ + ci;
        int chunk = k_abs >> 5;
        int k0 = k_abs & 31;
        int ks = k0 >> 4;
        int lane = ((co & 7) << 2) + ((k0 & 7) >> 1);
        int reg  = (k0 >> 3) & 1;
        int nt   = co >> 3;
        size_t di = (size_t)(e*NCHUNK + chunk)*2048 + ((ks*16 + nt)*32 + lane)*2 + reg;
        g_wBf[di] = h0 | (h1 << 16);
    }
    if (idx < NEX*C_) {
        int ex = idx >> 7, co = idx & 127;
        g_bias[idx] = (ex < 8) ? eb[idx] : sb[co];
    }
    if (idx < C_*9*E_) {             // gate weights: [ci][tap][e]
        int e = idx & 7;
        int r = idx >> 3;
        int t = r % 9, ci = r / 9;
        g_wG[idx] = gw[(e*C_ + ci)*9 + t];
    }
}

// ---------------- gate: fp32 NCHW conv(8), ci split across 8 warps --------
// Routing MUST stay fp32 on the ORIGINAL x (R7 lesson: fp16 flips top-2).
// lane = 32 consecutive pixels (1-wavefront tap loads); warp wy covers
// ci [wy*16, wy*16+16). Weights: uniform LDG.128 broadcasts from g_wG.
__global__ __launch_bounds__(256, 8)
void k_gate(const float* __restrict__ x, const float* __restrict__ gbias) {
    __shared__ float red[8][32][8];
    const int tid  = threadIdx.x;
    const int lane = tid & 31, wy = tid >> 5;
    const int pid  = blockIdx.x*32 + lane;
    int b = pid / HW_, hw = pid - b*HW_;
    int h = hw / W_, w = hw - h*W_;
    const float* xb = x + (size_t)b*C_*HW_ + hw;
    bool hm = h > 0, hp = h < H_-1, wm = w > 0, wp = w < W_-1;

    float acc[E_];
    #pragma unroll
    for (int e = 0; e < E_; e++) acc[e] = 0.f;

    const int ci0 = wy*16;
    #pragma unroll 2
    for (int cc = 0; cc < 16; cc++) {
        const int ci = ci0 + cc;
        const float* xp = xb + ci*HW_;
        float xv[9];
        xv[0] = (hm && wm) ? xp[-W_-1] : 0.f;
        xv[1] =  hm        ? xp[-W_]   : 0.f;
        xv[2] = (hm && wp) ? xp[-W_+1] : 0.f;
        xv[3] =  wm        ? xp[-1]    : 0.f;
        xv[4] =              xp[0];
        xv[5] =  wp        ? xp[1]     : 0.f;
        xv[6] = (hp && wm) ? xp[W_-1]  : 0.f;
        xv[7] =  hp        ? xp[W_]    : 0.f;
        xv[8] = (hp && wp) ? xp[W_+1]  : 0.f;
        const float4* wv = (const float4*)(g_wG + ci*72);
        #pragma unroll
        for (int t = 0; t < 9; t++) {
            float4 wa = wv[t*2], wb = wv[t*2 + 1];
            acc[0] = fmaf(xv[t], wa.x, acc[0]);
            acc[1] = fmaf(xv[t], wa.y, acc[1]);
            acc[2] = fmaf(xv[t], wa.z, acc[2]);
            acc[3] = fmaf(xv[t], wa.w, acc[3]);
            acc[4] = fmaf(xv[t], wb.x, acc[4]);
            acc[5] = fmaf(xv[t], wb.y, acc[5]);
            acc[6] = fmaf(xv[t], wb.z, acc[6]);
            acc[7] = fmaf(xv[t], wb.w, acc[7]);
        }
    }
    #pragma unroll
    for (int e = 0; e < E_; e++) red[wy][lane][e] = acc[e];
    __syncthreads();

    if (wy == 0) {
        float s[E_], bsc[E_];
        #pragma unroll
        for (int e = 0; e < E_; e++) {
            float a = red[0][lane][e];
            #pragma unroll
            for (int r = 1; r < 8; r++) a += red[r][lane][e];
            s[e]   = 1.f / (1.f + expf(-a));
            bsc[e] = s[e] + gbias[e];
        }
        int e0 = 0;
        #pragma unroll
        for (int e = 1; e < E_; e++) if (bsc[e] > bsc[e0]) e0 = e;
        int e1 = (e0 == 0) ? 1 : 0;
        #pragma unroll
        for (int e = 0; e < E_; e++) if (e != e0 && bsc[e] > bsc[e1]) e1 = e;
        float m = fmaxf(s[e0], s[e1]);
        float d0 = expf(s[e0]-m), d1 = expf(s[e1]-m);
        float inv = 1.f / (d0 + d1);
        int p0 = atomicAdd(&g_count[e0], 1);
        g_list[e0][p0] = (((unsigned long long)__float_as_uint(d0*inv)) << 32) | (unsigned)pid;
        int p1 = atomicAdd(&g_count[e1], 1);
        g_list[e1][p1] = (((unsigned long long)__float_as_uint(d1*inv)) << 32) | (unsigned)(pid | (1u<<20));
    }
}

// ---------------- fp16 mma.sync expert GEMM (pipelined, single-pass) ------
// CTA: 128 pixels x 128 couts, one expert. 8 warps in 2(M)x4(N).
__global__ __launch_bounds__(256, 2)
void k_mma() {
    const int e    = blockIdx.y;
    const int tile = blockIdx.x;
    const int n    = (e < 8) ? g_count[e] : P_;
    if (tile * 128 >= n) return;

    extern __shared__ uint32_t dsm[];
    uint32_t* sAp = dsm;          // 2 stages x 2048 u32
    uint32_t* sBp = dsm + 4096;   // 2 stages x 2048 u32
    __shared__ int   s_pid[128];
    __shared__ int   s_pp[128];
    __shared__ float s_wt[128];
    __shared__ float s_bias[128];

    const int tid = threadIdx.x;
    if (tid < 128) {
        int idx = tile*128 + tid;
        int pid = 0, slot = 0; float wt = 0.f;
        if (e < 8) {
            if (idx < n) {
                unsigned long long v = g_list[e][idx];
                wt   = __uint_as_float((unsigned)(v >> 32));
                unsigned lo = (unsigned)v;
                pid  = lo & 0xFFFFF;
                slot = (lo >> 20) & 1;
            }
        } else { pid = idx; wt = 1.f; slot = 2; }
        int b = pid / HW_, hw = pid - b*HW_;
        int h = hw / W_, w = hw - h*W_;
        s_pp[tid]   = (wt != 0.f) ? (b*HWP_ + (h+1)*WP_ + (w+1)) : (WP_ + 1);
        s_pid[tid]  = pid | (slot << 20);
        s_wt[tid]   = wt;
        s_bias[tid] = g_bias[e*C_ + tid];
    }
    __syncthreads();

    const int lane = tid & 31, wid = tid >> 5;
    const int wm = wid >> 2, wn = wid & 3;

    float c[4][4][4];
    #pragma unroll
    for (int i = 0; i < 4; i++)
        #pragma unroll
        for (int j = 0; j < 4; j++)
            #pragma unroll
            for (int k = 0; k < 4; k++) c[i][j][k] = 0.f;

    const int m_row = tid >> 3;      // A gather: 8 threads per pixel row
    const int kq    = tid & 7;       // each covers 4 ci (8 bytes fp16)
    const uint32_t sB_byte = smem_u32(sBp);
    const uint32_t* __restrict__ wbase = g_wBf + (size_t)e*NCHUNK*2048;

    uint2 pf[4];
    // ---- prologue: A chunk0 -> regs, B chunk0 -> sB stage0 via cp.async ----
    {
        const int off = -WP_ - 1;    // tap 0
        #pragma unroll
        for (int j = 0; j < 4; j++) {
            int m = m_row + j*32;
            pf[j] = *(const uint2*)(g_xh + (size_t)(s_pp[m] + off)*C_ + kq*4);
        }
        const uint4* bs = (const uint4*)wbase;
        #pragma unroll
        for (int j = 0; j < 2; j++)
            cp_async16(sB_byte + (tid + j*256)*16, bs + tid + j*256);
        CP_COMMIT();
    }

    for (int ch = 0; ch < NCHUNK; ch++) {
        const int st = ch & 1;
        uint32_t* sA = sAp + st*2048;
        uint32_t* sB = sBp + st*2048;

        // ---- STS A fragments from prefetched regs (already frag-order u32) ----
        {
            const int k0 = kq * 4;
            const int ks = k0 >> 4;
            const int la = ((k0 & 7) >> 1);
            const int rg_k = ((k0 >> 3) & 1) << 1;
            #pragma unroll
            for (int j = 0; j < 4; j++) {
                int m = m_row + j*32;
                int mt = m >> 4;
                int lane_a = ((m & 7) << 2) + la;
                int rg = ((m >> 3) & 1) + rg_k;
                int bi = ((ks*8 + mt)*32 + lane_a)*4 + rg;
                sA[bi]     = pf[j].x;   // (ci0, ci1)
                sA[bi + 4] = pf[j].y;   // (ci2, ci3)
            }
        }
        CP_WAIT0();          // B(ch) landed
        __syncthreads();     // sA[st] + sB[st] visible to all

        // ---- prefetch next chunk (overlaps mma below) ----
        if (ch + 1 < NCHUNK) {
            const int t = (ch+1) >> 2, ci0 = ((ch+1) & 3) * 32;
            const int off = (t/3 - 1)*WP_ + (t%3 - 1);
            #pragma unroll
            for (int j = 0; j < 4; j++) {
                int m = m_row + j*32;
                pf[j] = *(const uint2*)(g_xh + (size_t)(s_pp[m] + off)*C_ + ci0 + kq*4);
            }
            const uint4* bs = (const uint4*)(wbase + (size_t)(ch+1)*2048);
            const uint32_t dstb = sB_byte + (st^1)*8192;
            #pragma unroll
            for (int j = 0; j < 2; j++)
                cp_async16(dstb + (tid + j*256)*16, bs + tid + j*256);
            CP_COMMIT();
        }

        // ---- mma: single-pass fp16 ----
        #pragma unroll
        for (int ks = 0; ks < 2; ks++) {
            uint32_t bh[4][2];
            #pragma unroll
            for (int nt = 0; nt < 4; nt++) {
                int ng = wn*4 + nt;
                uint2 h2 = ((const uint2*)(sB + (ks*16 + ng)*64))[lane];
                bh[nt][0] = h2.x; bh[nt][1] = h2.y;
            }
            #pragma unroll
            for (int mt = 0; mt < 4; mt++) {
                int mg = wm*4 + mt;
                uint4 ah4 = ((const uint4*)(sA + (ks*8 + mg)*128))[lane];
                uint32_t ah[4] = {ah4.x, ah4.y, ah4.z, ah4.w};
                #pragma unroll
                for (int nt = 0; nt < 4; nt++)
                    mma_fp16(c[mt][nt], ah, bh[nt]);
            }
        }
        // no trailing sync: 2-stage rotation, single barrier per chunk.
    }

    // ---- epilogue: (acc + bias) * wt  ->  g_partial[slot][pid][co] ----
    #pragma unroll
    for (int mt = 0; mt < 4; mt++) {
        int r0 = wm*64 + mt*16 + (lane >> 2);
        #pragma unroll
        for (int half = 0; half < 2; half++) {
            int r = r0 + half*8;
            float wt = s_wt[r];
            if (wt != 0.f) {
                int pm  = s_pid[r];
                int pid = pm & 0xFFFFF;
                int slot = pm >> 20;
                float* dst = g_partial + ((size_t)slot*P_ + pid)*C_;
                #pragma unroll
                for (int nt = 0; nt < 4; nt++) {
                    int n0 = (wn*4 + nt)*8 + (lane & 3)*2;
                    float2 v;
                    v.x = (c[mt][nt][half*2 + 0] + s_bias[n0])     * wt;
                    v.y = (c[mt][nt][half*2 + 1] + s_bias[n0 + 1]) * wt;
                    *(float2*)(dst + n0) = v;
                }
            }
        }
    }
}

// ---------------- combine: out = p0 + p1 + p2 (transpose to NCHW) ---------
__global__ void k_combine(float* __restrict__ out) {
    __shared__ float t[32][33];
    int pid0 = blockIdx.x * 32, co0 = blockIdx.y * 32;
    int tid = threadIdx.x;
    #pragma unroll
    for (int r = 0; r < 4; r++) {
        int i = r*256 + tid;
        int pr = i >> 5, cl = i & 31;
        size_t o0 = ((size_t)(pid0 + pr))*C_ + co0 + cl;
        t[cl][pr] = g_partial[o0] + g_partial[(size_t)P_*C_ + o0]
                  + g_partial[2*(size_t)P_*C_ + o0];
    }
    __syncthreads();
    #pragma unroll
    for (int r = 0; r < 4; r++) {
        int i = r*256 + tid;
        int cl = i >> 5, pl = i & 31;
        int pid = pid0 + pl;
        int b = pid / HW_, hw = pid - b*HW_;
        out[((size_t)b*C_ + co0 + cl)*HW_ + hw] = t[cl][pl];
    }
}

// ---------------- launch ---------------------------------------------------
extern "C" void kernel_launch(void* const* d_in, const int* in_sizes, int n_in,
                              void* d_out, int out_size) {
    const float* x  = (const float*)d_in[0];
    const float* gw = (const float*)d_in[1];
    const float* gb = (const float*)d_in[2];
    const float* ew = (const float*)d_in[3];
    const float* eb = (const float*)d_in[4];
    const float* sw = (const float*)d_in[5];
    const float* sb = (const float*)d_in[6];
    float* out = (float*)d_out;

    cudaFuncSetAttribute(k_mma, cudaFuncAttributeMaxDynamicSharedMemorySize, 32768);

    k_init_halo<<<(4*388*32 + 255)/256, 256>>>();
    k_nhwc<<<dim3(HW_/32, C_/32, B_), 256>>>(x);
    k_repackB<<<(NEX*C_*9*64 + 255)/256, 256>>>(ew, sw, eb, sb, gw);
    k_gate<<<P_/32, 256>>>(x, gb);
    k_mma<<<dim3(P_/128, NEX), 256, 32768>>>();
    k_combine<<<dim3(P_/32, C_/32), 256>>>(out);
}

// round 16
// speedup vs baseline: 1.7930x; 1.0776x over previous
#include <cuda_runtime.h>
#include <cuda_bf16.h>
#include <cuda_fp16.h>
#include <cstdint>

#define B_    4
#define C_    128
#define H_    96
#define W_    96
#define HW_   (H_*W_)          // 9216
#define P_    (B_*HW_)         // 36864
#define E_    8
#define NEX   9
#define WP_   98
#define HP_   98
#define HWP_  (HP_*WP_)        // 9604
#define PPAD_ (B_*HWP_)        // 38416
#define NCHUNK 36              // K=1152 in chunks of 32

// ---------------- device globals (no allocation) --------------------------
__device__ __half   g_xh[PPAD_*C_];            // fp16 NHWC padded activations (9.8MB)
__device__ uint32_t g_wBf[NEX*NCHUNK*2048];    // fp16 B frags: [e][chunk]     (2.6MB)
__device__ float    g_wG[C_*9*E_];             // gate weights [ci][tap][e] (36KB)
__device__ float    g_bias[NEX*C_];
__device__ int      g_count[E_];
__device__ unsigned long long g_list[E_][P_];  // (w_bits<<32)|(slot<<20)|pid
__device__ float    g_partial[3*P_*C_];        // [slot][pid][co]  (56.6MB)

// ---------------- helpers --------------------------------------------------
__device__ __forceinline__ void mma_fp16(float* c, const uint32_t* a, const uint32_t* b) {
    asm volatile(
        "mma.sync.aligned.m16n8k16.row.col.f32.f16.f16.f32 "
        "{%0,%1,%2,%3}, {%4,%5,%6,%7}, {%8,%9}, {%0,%1,%2,%3};"
        : "+f"(c[0]), "+f"(c[1]), "+f"(c[2]), "+f"(c[3])
        : "r"(a[0]), "r"(a[1]), "r"(a[2]), "r"(a[3]), "r"(b[0]), "r"(b[1]));
}

__device__ __forceinline__ uint32_t smem_u32(const void* p) {
    uint32_t a;
    asm("{ .reg .u64 t; cvta.to.shared.u64 t, %1; cvt.u32.u64 %0, t; }" : "=r"(a) : "l"(p));
    return a;
}
__device__ __forceinline__ void cp_async16(uint32_t dst, const void* src) {
    asm volatile("cp.async.cg.shared.global [%0], [%1], 16;" :: "r"(dst), "l"(src) : "memory");
}
#define CP_COMMIT() asm volatile("cp.async.commit_group;" ::: "memory")
#define CP_WAIT0()  asm volatile("cp.async.wait_group 0;" ::: "memory")

// ---------------- init: counters + zero ONLY the halo ring ----------------
// 4 b * 388 halo px * 32 uint2 (128 ci) = 49664 items
__global__ void k_init_halo() {
    int g = blockIdx.x * blockDim.x + threadIdx.x;
    if (g < E_ && blockIdx.x == 0) g_count[g] = 0;
    if (g >= 4*388*32) return;
    int ci8 = g & 31;
    int j   = (g >> 5) % 388;
    int b   = g / (388*32);
    int hp, wp;
    if (j < 98)        { hp = 0;  wp = j; }
    else if (j < 196)  { hp = 97; wp = j - 98; }
    else { int k = j - 196; hp = 1 + (k >> 1); wp = (k & 1) ? 97 : 0; }
    int pp = b*HWP_ + hp*WP_ + wp;
    ((uint2*)(g_xh + (size_t)pp*C_))[ci8] = make_uint2(0u, 0u);
}

// ---------------- NCHW fp32 -> NHWC fp16 padded (interior) ----------------
__global__ void k_nhwc(const float* __restrict__ x) {
    __shared__ float t[32][33];
    int hw0 = blockIdx.x * 32, ci0 = blockIdx.y * 32, b = blockIdx.z;
    int tid = threadIdx.x;
    #pragma unroll
    for (int r = 0; r < 4; r++) {
        int ci = (tid >> 5) + r*8, hw = tid & 31;
        t[ci][hw] = x[((b*C_) + ci0 + ci)*HW_ + hw0 + hw];
    }
    __syncthreads();
    #pragma unroll
    for (int r = 0; r < 4; r++) {
        int hwl = (tid >> 5) + r*8, cil = tid & 31;
        int hw = hw0 + hwl, h = hw / W_, w = hw - h*W_;
        int pad = b*HWP_ + (h+1)*WP_ + (w+1);
        g_xh[(size_t)pad*C_ + ci0 + cil] = __float2half_rn(t[cil][hwl]);
    }
}

// weights -> fp16 mma fragment order + gate weights [ci][tap][e] ----------
__global__ void k_repackB(const float* __restrict__ ew, const float* __restrict__ sw,
                          const float* __restrict__ eb, const float* __restrict__ sb,
                          const float* __restrict__ gw) {
    int idx = blockIdx.x * blockDim.x + threadIdx.x;
    const int total = NEX*C_*9*64;
    if (idx < total) {
        int cip = idx & 63;
        int tap = (idx >> 6) % 9;
        int co  = (idx / (64*9)) & 127;
        int e   = idx / (64*9*C_);
        int ci  = cip * 2;
        float v0, v1;
        if (e < 8) {
            int base = ((e*C_ + co)*C_ + ci)*9 + tap;
            v0 = ew[base]; v1 = ew[base + 9];
        } else {
            int base = (co*C_ + ci)*9 + tap;
            v0 = sw[base]; v1 = sw[base + 9];
        }
        uint32_t h0 = (uint32_t)__half_as_ushort(__float2half_rn(v0));
        uint32_t h1 = (uint32_t)__half_as_ushort(__float2half_rn(v1));
        int k_abs = tap*C_ + ci;
        int chunk = k_abs >> 5;
        int k0 = k_abs & 31;
        int ks = k0 >> 4;
        int lane = ((co & 7) << 2) + ((k0 & 7) >> 1);
        int reg  = (k0 >> 3) & 1;
        int nt   = co >> 3;
        size_t di = (size_t)(e*NCHUNK + chunk)*2048 + ((ks*16 + nt)*32 + lane)*2 + reg;
        g_wBf[di] = h0 | (h1 << 16);
    }
    if (idx < NEX*C_) {
        int ex = idx >> 7, co = idx & 127;
        g_bias[idx] = (ex < 8) ? eb[idx] : sb[co];
    }
    if (idx < C_*9*E_) {             // gate weights: [ci][tap][e]
        int e = idx & 7;
        int r = idx >> 3;
        int t = r % 9, ci = r / 9;
        g_wG[idx] = gw[(e*C_ + ci)*9 + t];
    }
}

// ---------------- gate: fp32 NCHW conv(8), 4 px/lane, ci over 8 warps -----
// Routing MUST stay fp32 on the ORIGINAL x (R7 lesson: fp16 flips top-2).
// Block = 128 pixels. Warp wy covers ci [wy*16, wy*16+16); each lane owns
// 4 pixels (j*32+lane) so each (ci,tap) weight LDG.128 broadcast is reused
// 4x -> halves chip-wide L1 wavefronts vs 1 px/lane.
__global__ __launch_bounds__(256, 4)
void k_gate(const float* __restrict__ x, const float* __restrict__ gbias) {
    __shared__ float red[8][128][9];   // [ciChunk][px][e pad9] = 36 KB
    const int tid  = threadIdx.x;
    const int lane = tid & 31, wy = tid >> 5;
    const int pbase = blockIdx.x*128;

    const float* xc[4];
    unsigned msk[4];
    #pragma unroll
    for (int j = 0; j < 4; j++) {
        int pid = pbase + j*32 + lane;
        int b = pid / HW_, hw = pid - b*HW_;
        int h = hw / W_, w = hw - h*W_;
        xc[j] = x + (size_t)b*C_*HW_ + hw;
        bool hm = h > 0, hp = h < H_-1, wm = w > 0, wp = w < W_-1;
        msk[j] = (unsigned)((hm&&wm)      ) | ((unsigned)hm << 1) | ((unsigned)(hm&&wp) << 2)
               | ((unsigned)wm << 3) | (1u << 4) | ((unsigned)wp << 5)
               | ((unsigned)(hp&&wm) << 6) | ((unsigned)hp << 7) | ((unsigned)(hp&&wp) << 8);
    }
    const int offt[9] = {-W_-1, -W_, -W_+1, -1, 0, 1, W_-1, W_, W_+1};

    float acc[4][E_];
    #pragma unroll
    for (int j = 0; j < 4; j++)
        #pragma unroll
        for (int e = 0; e < E_; e++) acc[j][e] = 0.f;

    const int ci0 = wy*16;
    #pragma unroll 1
    for (int cc = 0; cc < 16; cc++) {
        const int ci = ci0 + cc;
        const float4* wv = (const float4*)(g_wG + ci*72);
        const float* xp0 = xc[0] + ci*HW_;
        const float* xp1 = xc[1] + ci*HW_;
        const float* xp2 = xc[2] + ci*HW_;
        const float* xp3 = xc[3] + ci*HW_;
        const float* xps[4] = {xp0, xp1, xp2, xp3};
        #pragma unroll
        for (int t = 0; t < 9; t++) {
            float4 wa = wv[t*2], wb = wv[t*2 + 1];
            #pragma unroll
            for (int j = 0; j < 4; j++) {
                float xv = ((msk[j] >> t) & 1) ? xps[j][offt[t]] : 0.f;
                acc[j][0] = fmaf(xv, wa.x, acc[j][0]);
                acc[j][1] = fmaf(xv, wa.y, acc[j][1]);
                acc[j][2] = fmaf(xv, wa.z, acc[j][2]);
                acc[j][3] = fmaf(xv, wa.w, acc[j][3]);
                acc[j][4] = fmaf(xv, wb.x, acc[j][4]);
                acc[j][5] = fmaf(xv, wb.y, acc[j][5]);
                acc[j][6] = fmaf(xv, wb.z, acc[j][6]);
                acc[j][7] = fmaf(xv, wb.w, acc[j][7]);
            }
        }
    }
    #pragma unroll
    for (int j = 0; j < 4; j++)
        #pragma unroll
        for (int e = 0; e < E_; e++) red[wy][j*32 + lane][e] = acc[j][e];
    __syncthreads();

    if (wy < 4) {
        const int px = wy*32 + lane;
        const int pid = pbase + px;
        float s[E_], bsc[E_];
        #pragma unroll
        for (int e = 0; e < E_; e++) {
            float a = red[0][px][e];
            #pragma unroll
            for (int r = 1; r < 8; r++) a += red[r][px][e];
            s[e]   = 1.f / (1.f + expf(-a));
            bsc[e] = s[e] + gbias[e];
        }
        int e0 = 0;
        #pragma unroll
        for (int e = 1; e < E_; e++) if (bsc[e] > bsc[e0]) e0 = e;
        int e1 = (e0 == 0) ? 1 : 0;
        #pragma unroll
        for (int e = 0; e < E_; e++) if (e != e0 && bsc[e] > bsc[e1]) e1 = e;
        float m = fmaxf(s[e0], s[e1]);
        float d0 = expf(s[e0]-m), d1 = expf(s[e1]-m);
        float inv = 1.f / (d0 + d1);
        int p0 = atomicAdd(&g_count[e0], 1);
        g_list[e0][p0] = (((unsigned long long)__float_as_uint(d0*inv)) << 32) | (unsigned)pid;
        int p1 = atomicAdd(&g_count[e1], 1);
        g_list[e1][p1] = (((unsigned long long)__float_as_uint(d1*inv)) << 32) | (unsigned)(pid | (1u<<20));
    }
}

// ---------------- fp16 mma.sync expert GEMM (pipelined, single-pass) ------
// CTA: 128 pixels x 128 couts, one expert. 8 warps in 2(M)x4(N).
__global__ __launch_bounds__(256, 2)
void k_mma() {
    const int e    = blockIdx.y;
    const int tile = blockIdx.x;
    const int n    = (e < 8) ? g_count[e] : P_;
    if (tile * 128 >= n) return;

    extern __shared__ uint32_t dsm[];
    uint32_t* sAp = dsm;          // 2 stages x 2048 u32
    uint32_t* sBp = dsm + 4096;   // 2 stages x 2048 u32
    __shared__ int   s_pid[128];
    __shared__ int   s_pp[128];
    __shared__ float s_wt[128];
    __shared__ float s_bias[128];

    const int tid = threadIdx.x;
    if (tid < 128) {
        int idx = tile*128 + tid;
        int pid = 0, slot = 0; float wt = 0.f;
        if (e < 8) {
            if (idx < n) {
                unsigned long long v = g_list[e][idx];
                wt   = __uint_as_float((unsigned)(v >> 32));
                unsigned lo = (unsigned)v;
                pid  = lo & 0xFFFFF;
                slot = (lo >> 20) & 1;
            }
        } else { pid = idx; wt = 1.f; slot = 2; }
        int b = pid / HW_, hw = pid - b*HW_;
        int h = hw / W_, w = hw - h*W_;
        s_pp[tid]   = (wt != 0.f) ? (b*HWP_ + (h+1)*WP_ + (w+1)) : (WP_ + 1);
        s_pid[tid]  = pid | (slot << 20);
        s_wt[tid]   = wt;
        s_bias[tid] = g_bias[e*C_ + tid];
    }
    __syncthreads();

    const int lane = tid & 31, wid = tid >> 5;
    const int wm = wid >> 2, wn = wid & 3;

    float c[4][4][4];
    #pragma unroll
    for (int i = 0; i < 4; i++)
        #pragma unroll
        for (int j = 0; j < 4; j++)
            #pragma unroll
            for (int k = 0; k < 4; k++) c[i][j][k] = 0.f;

    const int m_row = tid >> 3;      // A gather: 8 threads per pixel row
    const int kq    = tid & 7;       // each covers 4 ci (8 bytes fp16)
    const uint32_t sB_byte = smem_u32(sBp);
    const uint32_t* __restrict__ wbase = g_wBf + (size_t)e*NCHUNK*2048;

    uint2 pf[4];
    // ---- prologue: A chunk0 -> regs, B chunk0 -> sB stage0 via cp.async ----
    {
        const int off = -WP_ - 1;    // tap 0
        #pragma unroll
        for (int j = 0; j < 4; j++) {
            int m = m_row + j*32;
            pf[j] = *(const uint2*)(g_xh + (size_t)(s_pp[m] + off)*C_ + kq*4);
        }
        const uint4* bs = (const uint4*)wbase;
        #pragma unroll
        for (int j = 0; j < 2; j++)
            cp_async16(sB_byte + (tid + j*256)*16, bs + tid + j*256);
        CP_COMMIT();
    }

    for (int ch = 0; ch < NCHUNK; ch++) {
        const int st = ch & 1;
        uint32_t* sA = sAp + st*2048;
        uint32_t* sB = sBp + st*2048;

        // ---- STS A fragments from prefetched regs (already frag-order u32) ----
        {
            const int k0 = kq * 4;
            const int ks = k0 >> 4;
            const int la = ((k0 & 7) >> 1);
            const int rg_k = ((k0 >> 3) & 1) << 1;
            #pragma unroll
            for (int j = 0; j < 4; j++) {
                int m = m_row + j*32;
                int mt = m >> 4;
                int lane_a = ((m & 7) << 2) + la;
                int rg = ((m >> 3) & 1) + rg_k;
                int bi = ((ks*8 + mt)*32 + lane_a)*4 + rg;
                sA[bi]     = pf[j].x;   // (ci0, ci1)
                sA[bi + 4] = pf[j].y;   // (ci2, ci3)
            }
        }
        CP_WAIT0();          // B(ch) landed
        __syncthreads();     // sA[st] + sB[st] visible to all

        // ---- prefetch next chunk (overlaps mma below) ----
        if (ch + 1 < NCHUNK) {
            const int t = (ch+1) >> 2, ci0 = ((ch+1) & 3) * 32;
            const int off = (t/3 - 1)*WP_ + (t%3 - 1);
            #pragma unroll
            for (int j = 0; j < 4; j++) {
                int m = m_row + j*32;
                pf[j] = *(const uint2*)(g_xh + (size_t)(s_pp[m] + off)*C_ + ci0 + kq*4);
            }
            const uint4* bs = (const uint4*)(wbase + (size_t)(ch+1)*2048);
            const uint32_t dstb = sB_byte + (st^1)*8192;
            #pragma unroll
            for (int j = 0; j < 2; j++)
                cp_async16(dstb + (tid + j*256)*16, bs + tid + j*256);
            CP_COMMIT();
        }

        // ---- mma: single-pass fp16 ----
        #pragma unroll
        for (int ks = 0; ks < 2; ks++) {
            uint32_t bh[4][2];
            #pragma unroll
            for (int nt = 0; nt < 4; nt++) {
                int ng = wn*4 + nt;
                uint2 h2 = ((const uint2*)(sB + (ks*16 + ng)*64))[lane];
                bh[nt][0] = h2.x; bh[nt][1] = h2.y;
            }
            #pragma unroll
            for (int mt = 0; mt < 4; mt++) {
                int mg = wm*4 + mt;
                uint4 ah4 = ((const uint4*)(sA + (ks*8 + mg)*128))[lane];
                uint32_t ah[4] = {ah4.x, ah4.y, ah4.z, ah4.w};
                #pragma unroll
                for (int nt = 0; nt < 4; nt++)
                    mma_fp16(c[mt][nt], ah, bh[nt]);
            }
        }
        // no trailing sync: 2-stage rotation, single barrier per chunk.
    }

    // ---- epilogue: (acc + bias) * wt  ->  g_partial[slot][pid][co] ----
    #pragma unroll
    for (int mt = 0; mt < 4; mt++) {
        int r0 = wm*64 + mt*16 + (lane >> 2);
        #pragma unroll
        for (int half = 0; half < 2; half++) {
            int r = r0 + half*8;
            float wt = s_wt[r];
            if (wt != 0.f) {
                int pm  = s_pid[r];
                int pid = pm & 0xFFFFF;
                int slot = pm >> 20;
                float* dst = g_partial + ((size_t)slot*P_ + pid)*C_;
                #pragma unroll
                for (int nt = 0; nt < 4; nt++) {
                    int n0 = (wn*4 + nt)*8 + (lane & 3)*2;
                    float2 v;
                    v.x = (c[mt][nt][half*2 + 0] + s_bias[n0])     * wt;
                    v.y = (c[mt][nt][half*2 + 1] + s_bias[n0 + 1]) * wt;
                    *(float2*)(dst + n0) = v;
                }
            }
        }
    }
}

// ---------------- combine: out = p0 + p1 + p2 (transpose to NCHW) ---------
__global__ void k_combine(float* __restrict__ out) {
    __shared__ float t[32][33];
    int pid0 = blockIdx.x * 32, co0 = blockIdx.y * 32;
    int tid = threadIdx.x;
    #pragma unroll
    for (int r = 0; r < 4; r++) {
        int i = r*256 + tid;
        int pr = i >> 5, cl = i & 31;
        size_t o0 = ((size_t)(pid0 + pr))*C_ + co0 + cl;
        t[cl][pr] = g_partial[o0] + g_partial[(size_t)P_*C_ + o0]
                  + g_partial[2*(size_t)P_*C_ + o0];
    }
    __syncthreads();
    #pragma unroll
    for (int r = 0; r < 4; r++) {
        int i = r*256 + tid;
        int cl = i >> 5, pl = i & 31;
        int pid = pid0 + pl;
        int b = pid / HW_, hw = pid - b*HW_;
        out[((size_t)b*C_ + co0 + cl)*HW_ + hw] = t[cl][pl];
    }
}

// ---------------- launch ---------------------------------------------------
extern "C" void kernel_launch(void* const* d_in, const int* in_sizes, int n_in,
                              void* d_out, int out_size) {
    const float* x  = (const float*)d_in[0];
    const float* gw = (const float*)d_in[1];
    const float* gb = (const float*)d_in[2];
    const float* ew = (const float*)d_in[3];
    const float* eb = (const float*)d_in[4];
    const float* sw = (const float*)d_in[5];
    const float* sb = (const float*)d_in[6];
    float* out = (float*)d_out;

    cudaFuncSetAttribute(k_mma, cudaFuncAttributeMaxDynamicSharedMemorySize, 32768);

    k_init_halo<<<(4*388*32 + 255)/256, 256>>>();
    k_nhwc<<<dim3(HW_/32, C_/32, B_), 256>>>(x);
    k_repackB<<<(NEX*C_*9*64 + 255)/256, 256>>>(ew, sw, eb, sb, gw);
    k_gate<<<P_/128, 256>>>(x, gb);
    k_mma<<<dim3(P_/128, NEX), 256, 32768>>>();
    k_combine<<<dim3(P_/32, C_/32), 256>>>(out);
}